// round 15
// baseline (speedup 1.0000x reference)
#include <cuda_runtime.h>
#include <cuda_fp16.h>
#include <cstdint>
#include <cstring>

// Problem constants
#define B_ 16
#define N_ 1024
#define L_ 120
#define C_ 1024
#define H_ 16
#define DH_ 64

// Scratch (allocation-free rule: __device__ globals)
__device__ float g_q[B_ * N_ * C_];
__device__ float g_kv[B_ * L_ * 2 * C_];
__device__ float g_attn[B_ * N_ * C_];

// ---------------------------------------------------------------------------
// Helpers
// ---------------------------------------------------------------------------
__device__ __forceinline__ uint32_t smem_u32(const void* p) {
    uint32_t a;
    asm("{ .reg .u64 t; cvta.to.shared.u64 t, %1; cvt.u32.u64 %0, t; }"
        : "=r"(a) : "l"(p));
    return a;
}

#define LDM4(r, addr) \
    asm volatile("ldmatrix.sync.aligned.m8n8.x4.shared.b16 {%0,%1,%2,%3}, [%4];" \
                 : "=r"((r)[0]), "=r"((r)[1]), "=r"((r)[2]), "=r"((r)[3]) \
                 : "r"(addr))

#define LDM4T(r, addr) \
    asm volatile("ldmatrix.sync.aligned.m8n8.x4.trans.shared.b16 {%0,%1,%2,%3}, [%4];" \
                 : "=r"((r)[0]), "=r"((r)[1]), "=r"((r)[2]), "=r"((r)[3]) \
                 : "r"(addr))

#define MMAH16816(d, a, b0, b1) \
    asm volatile("mma.sync.aligned.m16n8k16.row.col.f32.f16.f16.f32 " \
                 "{%0,%1,%2,%3}, {%4,%5,%6,%7}, {%8,%9}, {%0,%1,%2,%3};" \
                 : "+f"((d)[0]), "+f"((d)[1]), "+f"((d)[2]), "+f"((d)[3]) \
                 : "r"((a)[0]), "r"((a)[1]), "r"((a)[2]), "r"((a)[3]), \
                   "r"(b0), "r"(b1))

__device__ __forceinline__ uint32_t pack_h2_hi(float a, float b, float& ra, float& rb) {
    __half2 h = __float22half2_rn(make_float2(a, b));
    float2 f = __half22float2(h);
    ra = a - f.x; rb = b - f.y;
    uint32_t u; memcpy(&u, &h, 4); return u;
}
__device__ __forceinline__ uint32_t pack_h2(float a, float b) {
    __half2 h = __float22half2_rn(make_float2(a, b));
    uint32_t u; memcpy(&u, &h, 4); return u;
}
__device__ __forceinline__ void h_store(uint32_t addr, float4 v) {
    uint32_t h0 = pack_h2(v.x, v.y);
    uint32_t h1 = pack_h2(v.z, v.w);
    asm volatile("st.shared.v2.b32 [%0], {%1, %2};" :: "r"(addr), "r"(h0), "r"(h1));
}
__device__ __forceinline__ void h_split_store(uint32_t hi_addr, uint32_t lo_addr, float4 v) {
    float r0, r1, r2, r3;
    uint32_t h0 = pack_h2_hi(v.x, v.y, r0, r1);
    uint32_t h1 = pack_h2_hi(v.z, v.w, r2, r3);
    uint32_t l0 = pack_h2(r0, r1), l1 = pack_h2(r2, r3);
    asm volatile("st.shared.v2.b32 [%0], {%1, %2};" :: "r"(hi_addr), "r"(h0), "r"(h1));
    asm volatile("st.shared.v2.b32 [%0], {%1, %2};" :: "r"(lo_addr), "r"(l0), "r"(l1));
}

// ---------------------------------------------------------------------------
// Tensor-core GEMM, fp16 2-pass split, BN=256 (64x64 warp tiles, 8 warps),
// DOUBLE-BUFFERED:  C = Ahi*(Bhi + Blo) + bias
// Per chunk: [prefetch c+1 -> regs] [MMA on stage s] [STS c+1 -> s^1] [sync]
// ---------------------------------------------------------------------------
#define BM 128
#define BN 256
#define BK 32
#define TPB 256
#define ROWB 80
#define A_TILE (128 * ROWB)             // 10240
#define B_TILE (256 * ROWB)             // 20480
#define SM_AH 0
#define SM_BHI A_TILE
#define SM_BLO (A_TILE + B_TILE)
#define STAGE (A_TILE + 2 * B_TILE)     // 51200
#define GEMM_SMEM (2 * STAGE)           // 102400

__global__ __launch_bounds__(TPB, 1)
void tc_gemm_nt_bias(const float* __restrict__ A,
                     const float* __restrict__ Bm,
                     const float* __restrict__ bias,
                     float* __restrict__ C,
                     int M, int N, int K)
{
    extern __shared__ char smem_raw[];
    const uint32_t sb = smem_u32(smem_raw);

    const int tid = threadIdx.x;
    const int wid = tid >> 5;
    const int l   = tid & 31;
    const int m0 = blockIdx.y * BM;
    const int n0 = blockIdx.x * BN;
    const int wm = (wid & 1) * 64;
    const int wn = (wid >> 1) * 64;

    const int ldRow = tid >> 3;        // 0..31 (+32 per i) — 8 threads/row, coalesced
    const int ldC4  = tid & 7;

    const uint32_t aOff = (uint32_t)((wm + (l & 15)) * ROWB + ((l >> 4) << 4));
    const uint32_t bOff = (uint32_t)((wn + (l & 7) + ((l >> 4) << 3)) * ROWB
                                     + (((l >> 3) & 1) << 4));

    float acc[4][8][4];
#pragma unroll
    for (int mt = 0; mt < 4; mt++)
#pragma unroll
        for (int nt = 0; nt < 8; nt++)
#pragma unroll
            for (int r = 0; r < 4; r++) acc[mt][nt][r] = 0.f;

    const int nch = K / BK;
    float4 ra[4], rb[8];

    // prologue: chunk 0 -> regs -> stage 0
#pragma unroll
    for (int i = 0; i < 4; i++)
        ra[i] = *(const float4*)(A + (size_t)(m0 + ldRow + i * 32) * K + ldC4 * 4);
#pragma unroll
    for (int i = 0; i < 8; i++)
        rb[i] = *(const float4*)(Bm + (size_t)(n0 + ldRow + i * 32) * K + ldC4 * 4);
#pragma unroll
    for (int i = 0; i < 4; i++) {
        uint32_t so = (uint32_t)((ldRow + i * 32) * ROWB + ldC4 * 8);
        h_store(sb + SM_AH + so, ra[i]);
    }
#pragma unroll
    for (int i = 0; i < 8; i++) {
        uint32_t so = (uint32_t)((ldRow + i * 32) * ROWB + ldC4 * 8);
        h_split_store(sb + SM_BHI + so, sb + SM_BLO + so, rb[i]);
    }
    __syncthreads();

    for (int c = 0; c < nch; c++) {
        const uint32_t st = sb + (uint32_t)(c & 1) * STAGE;

        // prefetch next chunk into regs (overlaps MMAs below)
        if (c + 1 < nch) {
            const int k0 = (c + 1) * BK;
#pragma unroll
            for (int i = 0; i < 4; i++)
                ra[i] = *(const float4*)(A + (size_t)(m0 + ldRow + i * 32) * K + k0 + ldC4 * 4);
#pragma unroll
            for (int i = 0; i < 8; i++)
                rb[i] = *(const float4*)(Bm + (size_t)(n0 + ldRow + i * 32) * K + k0 + ldC4 * 4);
        }

        // compute chunk c from stage st
#pragma unroll
        for (int ks = 0; ks < 2; ks++) {
            const uint32_t kso = (uint32_t)(ks * 32);
            uint32_t ah[4][4];
#pragma unroll
            for (int mt = 0; mt < 4; mt++)
                LDM4(ah[mt], st + SM_AH + aOff + mt * (16 * ROWB) + kso);
#pragma unroll
            for (int j = 0; j < 4; j++) {
                uint32_t bh[4], bl[4];
                LDM4(bh, st + SM_BHI + bOff + j * (16 * ROWB) + kso);
                LDM4(bl, st + SM_BLO + bOff + j * (16 * ROWB) + kso);
#pragma unroll
                for (int mt = 0; mt < 4; mt++) {
                    MMAH16816(acc[mt][2 * j],     ah[mt], bh[0], bh[1]);
                    MMAH16816(acc[mt][2 * j + 1], ah[mt], bh[2], bh[3]);
                }
#pragma unroll
                for (int mt = 0; mt < 4; mt++) {
                    MMAH16816(acc[mt][2 * j],     ah[mt], bl[0], bl[1]);
                    MMAH16816(acc[mt][2 * j + 1], ah[mt], bl[2], bl[3]);
                }
            }
        }

        // store next chunk into the other stage
        if (c + 1 < nch) {
            const uint32_t st2 = sb + (uint32_t)((c + 1) & 1) * STAGE;
#pragma unroll
            for (int i = 0; i < 4; i++) {
                uint32_t so = (uint32_t)((ldRow + i * 32) * ROWB + ldC4 * 8);
                h_store(st2 + SM_AH + so, ra[i]);
            }
#pragma unroll
            for (int i = 0; i < 8; i++) {
                uint32_t so = (uint32_t)((ldRow + i * 32) * ROWB + ldC4 * 8);
                h_split_store(st2 + SM_BHI + so, st2 + SM_BLO + so, rb[i]);
            }
        }
        __syncthreads();
    }

    // Epilogue
    const int cm = m0 + wm + (l >> 2);
    const int cn = n0 + wn + (l & 3) * 2;
#pragma unroll
    for (int mt = 0; mt < 4; mt++) {
#pragma unroll
        for (int nt = 0; nt < 8; nt++) {
            const int col = cn + nt * 8;
            const float b0 = bias[col], b1 = bias[col + 1];
            float* p0 = C + (size_t)(cm + mt * 16) * N + col;
            float* p1 = C + (size_t)(cm + mt * 16 + 8) * N + col;
            *(float2*)p0 = make_float2(acc[mt][nt][0] + b0, acc[mt][nt][1] + b1);
            *(float2*)p1 = make_float2(acc[mt][nt][2] + b0, acc[mt][nt][3] + b1);
        }
    }
}

// ---------------------------------------------------------------------------
// Tensor-core fused attention — fp16 2-pass (R12, unchanged; fp32 output).
// ---------------------------------------------------------------------------
#define AT_ROWB 144
#define AQ_H 0
#define AK_HI 18432
#define AK_LO 36864
#define AV_HI 55296
#define AV_LO 73728
#define AMK 92160
#define ATTN_SMEM 92672

__global__ __launch_bounds__(256, 1)
void attn_tc_kernel(const float* __restrict__ q,
                    const float* __restrict__ kv,
                    const int* __restrict__ mask,
                    float* __restrict__ out)
{
    extern __shared__ char smem_raw[];
    const uint32_t sb = smem_u32(smem_raw);
    const int tid = threadIdx.x, wid = tid >> 5, l = tid & 31;
    const int b = blockIdx.z, h = blockIdx.y, n0 = blockIdx.x * 128;
    const int wm = wid * 16;

    const float* qbase = q + ((size_t)(b * N_ + n0)) * C_ + h * DH_;
#pragma unroll
    for (int i = 0; i < 8; i++) {
        int f = i * 256 + tid;
        int row = f >> 4, c4 = f & 15;
        float4 v = *(const float4*)(qbase + (size_t)row * C_ + c4 * 4);
        uint32_t so = (uint32_t)(row * AT_ROWB + c4 * 8);
        h_store(sb + AQ_H + so, v);
    }
    const float* kvb = kv + (size_t)b * L_ * 2 * C_;
#pragma unroll
    for (int i = 0; i < 8; i++) {
        int f = i * 256 + tid;
        int row = f >> 4, c4 = f & 15;
        float4 v = make_float4(0.f, 0.f, 0.f, 0.f);
        if (row < L_) v = *(const float4*)(kvb + (size_t)row * (2 * C_) + h * DH_ + c4 * 4);
        uint32_t so = (uint32_t)(row * AT_ROWB + c4 * 8);
        h_split_store(sb + AK_HI + so, sb + AK_LO + so, v);
    }
#pragma unroll
    for (int i = 0; i < 8; i++) {
        int f = i * 256 + tid;
        int row = f >> 4, c4 = f & 15;
        float4 v = make_float4(0.f, 0.f, 0.f, 0.f);
        if (row < L_) v = *(const float4*)(kvb + (size_t)row * (2 * C_) + C_ + h * DH_ + c4 * 4);
        uint32_t so = (uint32_t)(row * AT_ROWB + c4 * 8);
        h_split_store(sb + AV_HI + so, sb + AV_LO + so, v);
    }
    if (tid < 128) {
        int m = (tid < L_) ? mask[b * L_ + tid] : 0;
        asm volatile("st.shared.b32 [%0], %1;" :: "r"(sb + AMK + tid * 4), "r"(m));
    }
    __syncthreads();

    float sacc[16][4];
#pragma unroll
    for (int nt = 0; nt < 16; nt++)
#pragma unroll
        for (int r = 0; r < 4; r++) sacc[nt][r] = 0.f;

    const uint32_t aOff = (uint32_t)((wm + (l & 15)) * AT_ROWB + ((l >> 4) << 4));
    const uint32_t bOffK = (uint32_t)(((l & 7) + ((l >> 4) << 3)) * AT_ROWB
                                      + (((l >> 3) & 1) << 4));
#pragma unroll
    for (int ks = 0; ks < 4; ks++) {
        const uint32_t kso = (uint32_t)(ks * 32);
        uint32_t ah[4];
        LDM4(ah, sb + AQ_H + aOff + kso);
#pragma unroll
        for (int j = 0; j < 8; j++) {
            uint32_t bh[4], bl[4];
            LDM4(bh, sb + AK_HI + bOffK + j * (16 * AT_ROWB) + kso);
            LDM4(bl, sb + AK_LO + bOffK + j * (16 * AT_ROWB) + kso);
            MMAH16816(sacc[2 * j],     ah, bh[0], bh[1]);
            MMAH16816(sacc[2 * j],     ah, bl[0], bl[1]);
            MMAH16816(sacc[2 * j + 1], ah, bh[2], bh[3]);
            MMAH16816(sacc[2 * j + 1], ah, bl[2], bl[3]);
        }
    }

    const int c0 = (l & 3) * 2;
    float mx0 = -1e30f, mx1 = -1e30f;
#pragma unroll
    for (int nt = 0; nt < 16; nt++) {
        int col = nt * 8 + c0;
        int m0_, m1_;
        asm volatile("ld.shared.b32 %0, [%1];" : "=r"(m0_) : "r"(sb + AMK + col * 4));
        asm volatile("ld.shared.b32 %0, [%1];" : "=r"(m1_) : "r"(sb + AMK + (col + 1) * 4));
        if (!m0_) { sacc[nt][0] = -1e30f; sacc[nt][2] = -1e30f; }
        if (!m1_) { sacc[nt][1] = -1e30f; sacc[nt][3] = -1e30f; }
        mx0 = fmaxf(mx0, fmaxf(sacc[nt][0], sacc[nt][1]));
        mx1 = fmaxf(mx1, fmaxf(sacc[nt][2], sacc[nt][3]));
    }
    mx0 = fmaxf(mx0, __shfl_xor_sync(0xFFFFFFFFu, mx0, 1));
    mx0 = fmaxf(mx0, __shfl_xor_sync(0xFFFFFFFFu, mx0, 2));
    mx1 = fmaxf(mx1, __shfl_xor_sync(0xFFFFFFFFu, mx1, 1));
    mx1 = fmaxf(mx1, __shfl_xor_sync(0xFFFFFFFFu, mx1, 2));

    const float cexp = 0.125f * 1.4426950408889634f;
    float sum0 = 0.f, sum1 = 0.f;
#pragma unroll
    for (int nt = 0; nt < 16; nt++) {
        float p0 = exp2f((sacc[nt][0] - mx0) * cexp);
        float p1 = exp2f((sacc[nt][1] - mx0) * cexp);
        float p2 = exp2f((sacc[nt][2] - mx1) * cexp);
        float p3 = exp2f((sacc[nt][3] - mx1) * cexp);
        sacc[nt][0] = p0; sacc[nt][1] = p1; sacc[nt][2] = p2; sacc[nt][3] = p3;
        sum0 += p0 + p1; sum1 += p2 + p3;
    }
    sum0 += __shfl_xor_sync(0xFFFFFFFFu, sum0, 1);
    sum0 += __shfl_xor_sync(0xFFFFFFFFu, sum0, 2);
    sum1 += __shfl_xor_sync(0xFFFFFFFFu, sum1, 1);
    sum1 += __shfl_xor_sync(0xFFFFFFFFu, sum1, 2);
    const float inv0 = 1.0f / sum0, inv1 = 1.0f / sum1;

    float oacc[8][4];
#pragma unroll
    for (int nt = 0; nt < 8; nt++)
#pragma unroll
        for (int r = 0; r < 4; r++) oacc[nt][r] = 0.f;

    const uint32_t vOff = (uint32_t)(((l & 7) + (((l >> 3) & 1) << 3)) * AT_ROWB
                                     + ((l >> 4) << 4));
#pragma unroll
    for (int j = 0; j < 8; j++) {
        uint32_t ph[4];
        ph[0] = pack_h2(sacc[2 * j][0],     sacc[2 * j][1]);
        ph[1] = pack_h2(sacc[2 * j][2],     sacc[2 * j][3]);
        ph[2] = pack_h2(sacc[2 * j + 1][0], sacc[2 * j + 1][1]);
        ph[3] = pack_h2(sacc[2 * j + 1][2], sacc[2 * j + 1][3]);
        const uint32_t rowOff = vOff + (uint32_t)(j * 16 * AT_ROWB);
#pragma unroll
        for (int jj = 0; jj < 4; jj++) {
            uint32_t vh[4], vl[4];
            LDM4T(vh, sb + AV_HI + rowOff + jj * 32);
            LDM4T(vl, sb + AV_LO + rowOff + jj * 32);
            MMAH16816(oacc[2 * jj],     ph, vh[0], vh[1]);
            MMAH16816(oacc[2 * jj],     ph, vl[0], vl[1]);
            MMAH16816(oacc[2 * jj + 1], ph, vh[2], vh[3]);
            MMAH16816(oacc[2 * jj + 1], ph, vl[2], vl[3]);
        }
    }

    const int grow = l >> 2;
    const int row0 = n0 + wm + grow, row1 = row0 + 8;
    float* ob = out + ((size_t)b * N_) * C_ + h * DH_;
#pragma unroll
    for (int nt = 0; nt < 8; nt++) {
        int col = nt * 8 + c0;
        *(float2*)(ob + (size_t)row0 * C_ + col) =
            make_float2(oacc[nt][0] * inv0, oacc[nt][1] * inv0);
        *(float2*)(ob + (size_t)row1 * C_ + col) =
            make_float2(oacc[nt][2] * inv1, oacc[nt][3] * inv1);
    }
}

// ---------------------------------------------------------------------------
// Launcher
// ---------------------------------------------------------------------------
extern "C" void kernel_launch(void* const* d_in, const int* in_sizes, int n_in,
                              void* d_out, int out_size)
{
    const float* x    = (const float*)d_in[0];
    const float* cond = (const float*)d_in[1];
    const int*   mask = (const int*)  d_in[2];
    const float* Wq   = (const float*)d_in[3];
    const float* bq   = (const float*)d_in[4];
    const float* Wkv  = (const float*)d_in[5];
    const float* bkv  = (const float*)d_in[6];
    const float* Wp   = (const float*)d_in[7];
    const float* bp   = (const float*)d_in[8];
    float* out = (float*)d_out;

    float *q_ptr, *kv_ptr, *attn_ptr;
    cudaGetSymbolAddress((void**)&q_ptr,    g_q);
    cudaGetSymbolAddress((void**)&kv_ptr,   g_kv);
    cudaGetSymbolAddress((void**)&attn_ptr, g_attn);

    cudaFuncSetAttribute(tc_gemm_nt_bias,
                         cudaFuncAttributeMaxDynamicSharedMemorySize, GEMM_SMEM);
    cudaFuncSetAttribute(attn_tc_kernel,
                         cudaFuncAttributeMaxDynamicSharedMemorySize, ATTN_SMEM);

    // KV projection: (1920, 2048) = cond @ Wkv^T + bkv
    {
        dim3 grid(2048 / BN, 1920 / BM);
        tc_gemm_nt_bias<<<grid, TPB, GEMM_SMEM>>>(cond, Wkv, bkv, kv_ptr, 1920, 2048, 1024);
    }
    // Q projection: (16384, 1024) = x @ Wq^T + bq
    {
        dim3 grid(1024 / BN, 16384 / BM);
        tc_gemm_nt_bias<<<grid, TPB, GEMM_SMEM>>>(x, Wq, bq, q_ptr, 16384, 1024, 1024);
    }
    // Fused tensor-core attention
    {
        dim3 grid(N_ / 128, H_, B_);
        attn_tc_kernel<<<grid, 256, ATTN_SMEM>>>(q_ptr, kv_ptr, mask, attn_ptr);
    }
    // Output projection: out = attn @ Wp^T + bp
    {
        dim3 grid(1024 / BN, 16384 / BM);
        tc_gemm_nt_bias<<<grid, TPB, GEMM_SMEM>>>(attn_ptr, Wp, bp, out, 16384, 1024, 1024);
    }
}

// round 17
// speedup vs baseline: 1.0071x; 1.0071x over previous
#include <cuda_runtime.h>
#include <cuda_fp16.h>
#include <cstdint>
#include <cstring>

// Problem constants
#define B_ 16
#define N_ 1024
#define L_ 120
#define C_ 1024
#define H_ 16
#define DH_ 64

// Scratch (allocation-free rule: __device__ globals)
__device__ __half g_qh[B_ * N_ * C_];        // Q projection output (fp16)
__device__ float  g_kv[B_ * L_ * 2 * C_];    // KV projection output (fp32)
__device__ __half g_attnh[B_ * N_ * C_];     // attention output (fp16)

// ---------------------------------------------------------------------------
// Helpers
// ---------------------------------------------------------------------------
__device__ __forceinline__ uint32_t smem_u32(const void* p) {
    uint32_t a;
    asm("{ .reg .u64 t; cvta.to.shared.u64 t, %1; cvt.u32.u64 %0, t; }"
        : "=r"(a) : "l"(p));
    return a;
}

#define LDM4(r, addr) \
    asm volatile("ldmatrix.sync.aligned.m8n8.x4.shared.b16 {%0,%1,%2,%3}, [%4];" \
                 : "=r"((r)[0]), "=r"((r)[1]), "=r"((r)[2]), "=r"((r)[3]) \
                 : "r"(addr))

#define LDM4T(r, addr) \
    asm volatile("ldmatrix.sync.aligned.m8n8.x4.trans.shared.b16 {%0,%1,%2,%3}, [%4];" \
                 : "=r"((r)[0]), "=r"((r)[1]), "=r"((r)[2]), "=r"((r)[3]) \
                 : "r"(addr))

#define MMAH16816(d, a, b0, b1) \
    asm volatile("mma.sync.aligned.m16n8k16.row.col.f32.f16.f16.f32 " \
                 "{%0,%1,%2,%3}, {%4,%5,%6,%7}, {%8,%9}, {%0,%1,%2,%3};" \
                 : "+f"((d)[0]), "+f"((d)[1]), "+f"((d)[2]), "+f"((d)[3]) \
                 : "r"((a)[0]), "r"((a)[1]), "r"((a)[2]), "r"((a)[3]), \
                   "r"(b0), "r"(b1))

#define STS128(addr, v) \
    asm volatile("st.shared.v4.b32 [%0], {%1, %2, %3, %4};" \
                 :: "r"(addr), "r"((v).x), "r"((v).y), "r"((v).z), "r"((v).w))

__device__ __forceinline__ uint32_t pack_h2_hi(float a, float b, float& ra, float& rb) {
    __half2 h = __float22half2_rn(make_float2(a, b));
    float2 f = __half22float2(h);
    ra = a - f.x; rb = b - f.y;
    uint32_t u; memcpy(&u, &h, 4); return u;
}
__device__ __forceinline__ uint32_t pack_h2(float a, float b) {
    __half2 h = __float22half2_rn(make_float2(a, b));
    uint32_t u; memcpy(&u, &h, 4); return u;
}
__device__ __forceinline__ void h_store(uint32_t addr, float4 v) {
    uint32_t h0 = pack_h2(v.x, v.y);
    uint32_t h1 = pack_h2(v.z, v.w);
    asm volatile("st.shared.v2.b32 [%0], {%1, %2};" :: "r"(addr), "r"(h0), "r"(h1));
}
__device__ __forceinline__ void h_split_store(uint32_t hi_addr, uint32_t lo_addr, float4 v) {
    float r0, r1, r2, r3;
    uint32_t h0 = pack_h2_hi(v.x, v.y, r0, r1);
    uint32_t h1 = pack_h2_hi(v.z, v.w, r2, r3);
    uint32_t l0 = pack_h2(r0, r1), l1 = pack_h2(r2, r3);
    asm volatile("st.shared.v2.b32 [%0], {%1, %2};" :: "r"(hi_addr), "r"(h0), "r"(h1));
    asm volatile("st.shared.v2.b32 [%0], {%1, %2};" :: "r"(lo_addr), "r"(l0), "r"(l1));
}

// ---------------------------------------------------------------------------
// GEMM tile config (R14-proven): BM=128, BN=256, 64x64 warp tiles, 8 warps,
// single-buffer smem, register prefetch, in-kernel fp16 split, pass-major.
// ---------------------------------------------------------------------------
#define BM 128
#define BN 256
#define BK 32
#define TPB 256
#define ROWB 80
#define A_TILE (128 * ROWB)             // 10240
#define B_TILE (256 * ROWB)             // 20480
#define SM_AH 0
#define SM_BHI A_TILE
#define SM_BLO (A_TILE + B_TILE)
#define GEMM_SMEM (A_TILE + 2 * B_TILE) // 51200

// --------------------- Variant 1: fp32 A, fp32 C (KV-proj) -----------------
__global__ __launch_bounds__(TPB, 1)
void tc_gemm_f32a_f32c(const float* __restrict__ A,
                       const float* __restrict__ Bm,
                       const float* __restrict__ bias,
                       float* __restrict__ C,
                       int M, int N, int K)
{
    extern __shared__ char smem_raw[];
    const uint32_t sb = smem_u32(smem_raw);
    const int tid = threadIdx.x, wid = tid >> 5, l = tid & 31;
    const int m0 = blockIdx.y * BM, n0 = blockIdx.x * BN;
    const int wm = (wid & 1) * 64, wn = (wid >> 1) * 64;
    const int ldRow = tid >> 3, ldC4 = tid & 7;

    const uint32_t aOff = (uint32_t)((wm + (l & 15)) * ROWB + ((l >> 4) << 4));
    const uint32_t bOff = (uint32_t)((wn + (l & 7) + ((l >> 4) << 3)) * ROWB
                                     + (((l >> 3) & 1) << 4));

    float acc[4][8][4];
#pragma unroll
    for (int mt = 0; mt < 4; mt++)
#pragma unroll
        for (int nt = 0; nt < 8; nt++)
#pragma unroll
            for (int r = 0; r < 4; r++) acc[mt][nt][r] = 0.f;

    const int nch = K / BK;
    float4 ra[4], rb[8];
#pragma unroll
    for (int i = 0; i < 4; i++)
        ra[i] = *(const float4*)(A + (size_t)(m0 + ldRow + i * 32) * K + ldC4 * 4);
#pragma unroll
    for (int i = 0; i < 8; i++)
        rb[i] = *(const float4*)(Bm + (size_t)(n0 + ldRow + i * 32) * K + ldC4 * 4);

    for (int c = 0; c < nch; c++) {
#pragma unroll
        for (int i = 0; i < 4; i++) {
            uint32_t so = (uint32_t)((ldRow + i * 32) * ROWB + ldC4 * 8);
            h_store(sb + SM_AH + so, ra[i]);
        }
#pragma unroll
        for (int i = 0; i < 8; i++) {
            uint32_t so = (uint32_t)((ldRow + i * 32) * ROWB + ldC4 * 8);
            h_split_store(sb + SM_BHI + so, sb + SM_BLO + so, rb[i]);
        }
        __syncthreads();

        if (c + 1 < nch) {
            const int k0 = (c + 1) * BK;
#pragma unroll
            for (int i = 0; i < 4; i++)
                ra[i] = *(const float4*)(A + (size_t)(m0 + ldRow + i * 32) * K + k0 + ldC4 * 4);
#pragma unroll
            for (int i = 0; i < 8; i++)
                rb[i] = *(const float4*)(Bm + (size_t)(n0 + ldRow + i * 32) * K + k0 + ldC4 * 4);
        }

#pragma unroll
        for (int ks = 0; ks < 2; ks++) {
            const uint32_t kso = (uint32_t)(ks * 32);
            uint32_t ah[4][4];
#pragma unroll
            for (int mt = 0; mt < 4; mt++)
                LDM4(ah[mt], sb + SM_AH + aOff + mt * (16 * ROWB) + kso);
#pragma unroll
            for (int j = 0; j < 4; j++) {
                uint32_t bh[4], bl[4];
                LDM4(bh, sb + SM_BHI + bOff + j * (16 * ROWB) + kso);
                LDM4(bl, sb + SM_BLO + bOff + j * (16 * ROWB) + kso);
#pragma unroll
                for (int mt = 0; mt < 4; mt++) {
                    MMAH16816(acc[mt][2 * j],     ah[mt], bh[0], bh[1]);
                    MMAH16816(acc[mt][2 * j + 1], ah[mt], bh[2], bh[3]);
                }
#pragma unroll
                for (int mt = 0; mt < 4; mt++) {
                    MMAH16816(acc[mt][2 * j],     ah[mt], bl[0], bl[1]);
                    MMAH16816(acc[mt][2 * j + 1], ah[mt], bl[2], bl[3]);
                }
            }
        }
        __syncthreads();
    }

    const int cm = m0 + wm + (l >> 2);
    const int cn = n0 + wn + (l & 3) * 2;
#pragma unroll
    for (int mt = 0; mt < 4; mt++)
#pragma unroll
        for (int nt = 0; nt < 8; nt++) {
            const int col = cn + nt * 8;
            const float b0 = bias[col], b1 = bias[col + 1];
            float* p0 = C + (size_t)(cm + mt * 16) * N + col;
            float* p1 = C + (size_t)(cm + mt * 16 + 8) * N + col;
            *(float2*)p0 = make_float2(acc[mt][nt][0] + b0, acc[mt][nt][1] + b1);
            *(float2*)p1 = make_float2(acc[mt][nt][2] + b0, acc[mt][nt][3] + b1);
        }
}

// --------------------- Variant 2: fp32 A, fp16 C (Q-proj) ------------------
__global__ __launch_bounds__(TPB, 1)
void tc_gemm_f32a_f16c(const float* __restrict__ A,
                       const float* __restrict__ Bm,
                       const float* __restrict__ bias,
                       __half* __restrict__ C,
                       int M, int N, int K)
{
    extern __shared__ char smem_raw[];
    const uint32_t sb = smem_u32(smem_raw);
    const int tid = threadIdx.x, wid = tid >> 5, l = tid & 31;
    const int m0 = blockIdx.y * BM, n0 = blockIdx.x * BN;
    const int wm = (wid & 1) * 64, wn = (wid >> 1) * 64;
    const int ldRow = tid >> 3, ldC4 = tid & 7;

    const uint32_t aOff = (uint32_t)((wm + (l & 15)) * ROWB + ((l >> 4) << 4));
    const uint32_t bOff = (uint32_t)((wn + (l & 7) + ((l >> 4) << 3)) * ROWB
                                     + (((l >> 3) & 1) << 4));

    float acc[4][8][4];
#pragma unroll
    for (int mt = 0; mt < 4; mt++)
#pragma unroll
        for (int nt = 0; nt < 8; nt++)
#pragma unroll
            for (int r = 0; r < 4; r++) acc[mt][nt][r] = 0.f;

    const int nch = K / BK;
    float4 ra[4], rb[8];
#pragma unroll
    for (int i = 0; i < 4; i++)
        ra[i] = *(const float4*)(A + (size_t)(m0 + ldRow + i * 32) * K + ldC4 * 4);
#pragma unroll
    for (int i = 0; i < 8; i++)
        rb[i] = *(const float4*)(Bm + (size_t)(n0 + ldRow + i * 32) * K + ldC4 * 4);

    for (int c = 0; c < nch; c++) {
#pragma unroll
        for (int i = 0; i < 4; i++) {
            uint32_t so = (uint32_t)((ldRow + i * 32) * ROWB + ldC4 * 8);
            h_store(sb + SM_AH + so, ra[i]);
        }
#pragma unroll
        for (int i = 0; i < 8; i++) {
            uint32_t so = (uint32_t)((ldRow + i * 32) * ROWB + ldC4 * 8);
            h_split_store(sb + SM_BHI + so, sb + SM_BLO + so, rb[i]);
        }
        __syncthreads();

        if (c + 1 < nch) {
            const int k0 = (c + 1) * BK;
#pragma unroll
            for (int i = 0; i < 4; i++)
                ra[i] = *(const float4*)(A + (size_t)(m0 + ldRow + i * 32) * K + k0 + ldC4 * 4);
#pragma unroll
            for (int i = 0; i < 8; i++)
                rb[i] = *(const float4*)(Bm + (size_t)(n0 + ldRow + i * 32) * K + k0 + ldC4 * 4);
        }

#pragma unroll
        for (int ks = 0; ks < 2; ks++) {
            const uint32_t kso = (uint32_t)(ks * 32);
            uint32_t ah[4][4];
#pragma unroll
            for (int mt = 0; mt < 4; mt++)
                LDM4(ah[mt], sb + SM_AH + aOff + mt * (16 * ROWB) + kso);
#pragma unroll
            for (int j = 0; j < 4; j++) {
                uint32_t bh[4], bl[4];
                LDM4(bh, sb + SM_BHI + bOff + j * (16 * ROWB) + kso);
                LDM4(bl, sb + SM_BLO + bOff + j * (16 * ROWB) + kso);
#pragma unroll
                for (int mt = 0; mt < 4; mt++) {
                    MMAH16816(acc[mt][2 * j],     ah[mt], bh[0], bh[1]);
                    MMAH16816(acc[mt][2 * j + 1], ah[mt], bh[2], bh[3]);
                }
#pragma unroll
                for (int mt = 0; mt < 4; mt++) {
                    MMAH16816(acc[mt][2 * j],     ah[mt], bl[0], bl[1]);
                    MMAH16816(acc[mt][2 * j + 1], ah[mt], bl[2], bl[3]);
                }
            }
        }
        __syncthreads();
    }

    const int cm = m0 + wm + (l >> 2);
    const int cn = n0 + wn + (l & 3) * 2;
#pragma unroll
    for (int mt = 0; mt < 4; mt++)
#pragma unroll
        for (int nt = 0; nt < 8; nt++) {
            const int col = cn + nt * 8;
            const float b0 = bias[col], b1 = bias[col + 1];
            *(uint32_t*)(C + (size_t)(cm + mt * 16) * N + col) =
                pack_h2(acc[mt][nt][0] + b0, acc[mt][nt][1] + b1);
            *(uint32_t*)(C + (size_t)(cm + mt * 16 + 8) * N + col) =
                pack_h2(acc[mt][nt][2] + b0, acc[mt][nt][3] + b1);
        }
}

// --------------------- Variant 3: fp16 A, fp32 C (out-proj) ----------------
__global__ __launch_bounds__(TPB, 1)
void tc_gemm_f16a_f32c(const __half* __restrict__ A,
                       const float* __restrict__ Bm,
                       const float* __restrict__ bias,
                       float* __restrict__ C,
                       int M, int N, int K)
{
    extern __shared__ char smem_raw[];
    const uint32_t sb = smem_u32(smem_raw);
    const int tid = threadIdx.x, wid = tid >> 5, l = tid & 31;
    const int m0 = blockIdx.y * BM, n0 = blockIdx.x * BN;
    const int wm = (wid & 1) * 64, wn = (wid >> 1) * 64;
    const int ldRow = tid >> 3, ldC4 = tid & 7;           // B mapping (fp32)
    const int laRow = tid >> 2, laSeg = (tid & 3) * 8;    // A mapping (fp16, 64B rows)

    const uint32_t aOff = (uint32_t)((wm + (l & 15)) * ROWB + ((l >> 4) << 4));
    const uint32_t bOff = (uint32_t)((wn + (l & 7) + ((l >> 4) << 3)) * ROWB
                                     + (((l >> 3) & 1) << 4));

    float acc[4][8][4];
#pragma unroll
    for (int mt = 0; mt < 4; mt++)
#pragma unroll
        for (int nt = 0; nt < 8; nt++)
#pragma unroll
            for (int r = 0; r < 4; r++) acc[mt][nt][r] = 0.f;

    const int nch = K / BK;
    uint4 ua[2];
    float4 rb[8];
#pragma unroll
    for (int i = 0; i < 2; i++)
        ua[i] = *(const uint4*)(A + (size_t)(m0 + laRow + i * 64) * K + laSeg);
#pragma unroll
    for (int i = 0; i < 8; i++)
        rb[i] = *(const float4*)(Bm + (size_t)(n0 + ldRow + i * 32) * K + ldC4 * 4);

    for (int c = 0; c < nch; c++) {
#pragma unroll
        for (int i = 0; i < 2; i++) {
            uint32_t so = (uint32_t)((laRow + i * 64) * ROWB + laSeg * 2);
            STS128(sb + SM_AH + so, ua[i]);
        }
#pragma unroll
        for (int i = 0; i < 8; i++) {
            uint32_t so = (uint32_t)((ldRow + i * 32) * ROWB + ldC4 * 8);
            h_split_store(sb + SM_BHI + so, sb + SM_BLO + so, rb[i]);
        }
        __syncthreads();

        if (c + 1 < nch) {
            const int k0 = (c + 1) * BK;
#pragma unroll
            for (int i = 0; i < 2; i++)
                ua[i] = *(const uint4*)(A + (size_t)(m0 + laRow + i * 64) * K + k0 + laSeg);
#pragma unroll
            for (int i = 0; i < 8; i++)
                rb[i] = *(const float4*)(Bm + (size_t)(n0 + ldRow + i * 32) * K + k0 + ldC4 * 4);
        }

#pragma unroll
        for (int ks = 0; ks < 2; ks++) {
            const uint32_t kso = (uint32_t)(ks * 32);
            uint32_t ah[4][4];
#pragma unroll
            for (int mt = 0; mt < 4; mt++)
                LDM4(ah[mt], sb + SM_AH + aOff + mt * (16 * ROWB) + kso);
#pragma unroll
            for (int j = 0; j < 4; j++) {
                uint32_t bh[4], bl[4];
                LDM4(bh, sb + SM_BHI + bOff + j * (16 * ROWB) + kso);
                LDM4(bl, sb + SM_BLO + bOff + j * (16 * ROWB) + kso);
#pragma unroll
                for (int mt = 0; mt < 4; mt++) {
                    MMAH16816(acc[mt][2 * j],     ah[mt], bh[0], bh[1]);
                    MMAH16816(acc[mt][2 * j + 1], ah[mt], bh[2], bh[3]);
                }
#pragma unroll
                for (int mt = 0; mt < 4; mt++) {
                    MMAH16816(acc[mt][2 * j],     ah[mt], bl[0], bl[1]);
                    MMAH16816(acc[mt][2 * j + 1], ah[mt], bl[2], bl[3]);
                }
            }
        }
        __syncthreads();
    }

    const int cm = m0 + wm + (l >> 2);
    const int cn = n0 + wn + (l & 3) * 2;
#pragma unroll
    for (int mt = 0; mt < 4; mt++)
#pragma unroll
        for (int nt = 0; nt < 8; nt++) {
            const int col = cn + nt * 8;
            const float b0 = bias[col], b1 = bias[col + 1];
            float* p0 = C + (size_t)(cm + mt * 16) * N + col;
            float* p1 = C + (size_t)(cm + mt * 16 + 8) * N + col;
            *(float2*)p0 = make_float2(acc[mt][nt][0] + b0, acc[mt][nt][1] + b1);
            *(float2*)p1 = make_float2(acc[mt][nt][2] + b0, acc[mt][nt][3] + b1);
        }
}

// ---------------------------------------------------------------------------
// Tensor-core fused attention — fp16 2-pass; fp16 Q in, fp16 O out.
// (FIXED Q loader: full 128x64 tile = 1024 uint4 via linear indexing.)
// ---------------------------------------------------------------------------
#define AT_ROWB 144
#define AQ_H 0
#define AK_HI 18432
#define AK_LO 36864
#define AV_HI 55296
#define AV_LO 73728
#define AMK 92160
#define ATTN_SMEM 92672

__global__ __launch_bounds__(256, 1)
void attn_tc_kernel(const __half* __restrict__ qh,
                    const float* __restrict__ kv,
                    const int* __restrict__ mask,
                    __half* __restrict__ outh)
{
    extern __shared__ char smem_raw[];
    const uint32_t sb = smem_u32(smem_raw);
    const int tid = threadIdx.x, wid = tid >> 5, l = tid & 31;
    const int b = blockIdx.z, h = blockIdx.y, n0 = blockIdx.x * 128;
    const int wm = wid * 16;

    // Q (fp16, 128 rows x 64 halves = 1024 uint4): linear uint4 copy, no CVT
    const __half* qbase = qh + ((size_t)(b * N_ + n0)) * C_ + h * DH_;
#pragma unroll
    for (int i = 0; i < 4; i++) {
        int u = i * 256 + tid;          // 0..1023
        int row = u >> 3;               // 8 uint4 per row
        int col8 = u & 7;               // uint4 index within row (8 halves each)
        uint4 v = *(const uint4*)(qbase + (size_t)row * C_ + col8 * 8);
        STS128(sb + AQ_H + (uint32_t)(row * AT_ROWB + col8 * 16), v);
    }
    // K (120x64 fp32, zero-pad) -> fp16 hi/lo
    const float* kvb = kv + (size_t)b * L_ * 2 * C_;
#pragma unroll
    for (int i = 0; i < 8; i++) {
        int f = i * 256 + tid;
        int row = f >> 4, c4 = f & 15;
        float4 v = make_float4(0.f, 0.f, 0.f, 0.f);
        if (row < L_) v = *(const float4*)(kvb + (size_t)row * (2 * C_) + h * DH_ + c4 * 4);
        uint32_t so = (uint32_t)(row * AT_ROWB + c4 * 8);
        h_split_store(sb + AK_HI + so, sb + AK_LO + so, v);
    }
    // V row-major (120x64 fp32, zero-pad) -> fp16 hi/lo
#pragma unroll
    for (int i = 0; i < 8; i++) {
        int f = i * 256 + tid;
        int row = f >> 4, c4 = f & 15;
        float4 v = make_float4(0.f, 0.f, 0.f, 0.f);
        if (row < L_) v = *(const float4*)(kvb + (size_t)row * (2 * C_) + C_ + h * DH_ + c4 * 4);
        uint32_t so = (uint32_t)(row * AT_ROWB + c4 * 8);
        h_split_store(sb + AV_HI + so, sb + AV_LO + so, v);
    }
    if (tid < 128) {
        int m = (tid < L_) ? mask[b * L_ + tid] : 0;
        asm volatile("st.shared.b32 [%0], %1;" :: "r"(sb + AMK + tid * 4), "r"(m));
    }
    __syncthreads();

    float sacc[16][4];
#pragma unroll
    for (int nt = 0; nt < 16; nt++)
#pragma unroll
        for (int r = 0; r < 4; r++) sacc[nt][r] = 0.f;

    const uint32_t aOff = (uint32_t)((wm + (l & 15)) * AT_ROWB + ((l >> 4) << 4));
    const uint32_t bOffK = (uint32_t)(((l & 7) + ((l >> 4) << 3)) * AT_ROWB
                                      + (((l >> 3) & 1) << 4));
#pragma unroll
    for (int ks = 0; ks < 4; ks++) {
        const uint32_t kso = (uint32_t)(ks * 32);
        uint32_t ah[4];
        LDM4(ah, sb + AQ_H + aOff + kso);
#pragma unroll
        for (int j = 0; j < 8; j++) {
            uint32_t bh[4], bl[4];
            LDM4(bh, sb + AK_HI + bOffK + j * (16 * AT_ROWB) + kso);
            LDM4(bl, sb + AK_LO + bOffK + j * (16 * AT_ROWB) + kso);
            MMAH16816(sacc[2 * j],     ah, bh[0], bh[1]);
            MMAH16816(sacc[2 * j],     ah, bl[0], bl[1]);
            MMAH16816(sacc[2 * j + 1], ah, bh[2], bh[3]);
            MMAH16816(sacc[2 * j + 1], ah, bl[2], bl[3]);
        }
    }

    const int c0 = (l & 3) * 2;
    float mx0 = -1e30f, mx1 = -1e30f;
#pragma unroll
    for (int nt = 0; nt < 16; nt++) {
        int col = nt * 8 + c0;
        int m0_, m1_;
        asm volatile("ld.shared.b32 %0, [%1];" : "=r"(m0_) : "r"(sb + AMK + col * 4));
        asm volatile("ld.shared.b32 %0, [%1];" : "=r"(m1_) : "r"(sb + AMK + (col + 1) * 4));
        if (!m0_) { sacc[nt][0] = -1e30f; sacc[nt][2] = -1e30f; }
        if (!m1_) { sacc[nt][1] = -1e30f; sacc[nt][3] = -1e30f; }
        mx0 = fmaxf(mx0, fmaxf(sacc[nt][0], sacc[nt][1]));
        mx1 = fmaxf(mx1, fmaxf(sacc[nt][2], sacc[nt][3]));
    }
    mx0 = fmaxf(mx0, __shfl_xor_sync(0xFFFFFFFFu, mx0, 1));
    mx0 = fmaxf(mx0, __shfl_xor_sync(0xFFFFFFFFu, mx0, 2));
    mx1 = fmaxf(mx1, __shfl_xor_sync(0xFFFFFFFFu, mx1, 1));
    mx1 = fmaxf(mx1, __shfl_xor_sync(0xFFFFFFFFu, mx1, 2));

    const float cexp = 0.125f * 1.4426950408889634f;
    float sum0 = 0.f, sum1 = 0.f;
#pragma unroll
    for (int nt = 0; nt < 16; nt++) {
        float p0 = exp2f((sacc[nt][0] - mx0) * cexp);
        float p1 = exp2f((sacc[nt][1] - mx0) * cexp);
        float p2 = exp2f((sacc[nt][2] - mx1) * cexp);
        float p3 = exp2f((sacc[nt][3] - mx1) * cexp);
        sacc[nt][0] = p0; sacc[nt][1] = p1; sacc[nt][2] = p2; sacc[nt][3] = p3;
        sum0 += p0 + p1; sum1 += p2 + p3;
    }
    sum0 += __shfl_xor_sync(0xFFFFFFFFu, sum0, 1);
    sum0 += __shfl_xor_sync(0xFFFFFFFFu, sum0, 2);
    sum1 += __shfl_xor_sync(0xFFFFFFFFu, sum1, 1);
    sum1 += __shfl_xor_sync(0xFFFFFFFFu, sum1, 2);
    const float inv0 = 1.0f / sum0, inv1 = 1.0f / sum1;

    float oacc[8][4];
#pragma unroll
    for (int nt = 0; nt < 8; nt++)
#pragma unroll
        for (int r = 0; r < 4; r++) oacc[nt][r] = 0.f;

    const uint32_t vOff = (uint32_t)(((l & 7) + (((l >> 3) & 1) << 3)) * AT_ROWB
                                     + ((l >> 4) << 4));
#pragma unroll
    for (int j = 0; j < 8; j++) {
        uint32_t ph[4];
        ph[0] = pack_h2(sacc[2 * j][0],     sacc[2 * j][1]);
        ph[1] = pack_h2(sacc[2 * j][2],     sacc[2 * j][3]);
        ph[2] = pack_h2(sacc[2 * j + 1][0], sacc[2 * j + 1][1]);
        ph[3] = pack_h2(sacc[2 * j + 1][2], sacc[2 * j + 1][3]);
        const uint32_t rowOff = vOff + (uint32_t)(j * 16 * AT_ROWB);
#pragma unroll
        for (int jj = 0; jj < 4; jj++) {
            uint32_t vh[4], vl[4];
            LDM4T(vh, sb + AV_HI + rowOff + jj * 32);
            LDM4T(vl, sb + AV_LO + rowOff + jj * 32);
            MMAH16816(oacc[2 * jj],     ph, vh[0], vh[1]);
            MMAH16816(oacc[2 * jj],     ph, vl[0], vl[1]);
            MMAH16816(oacc[2 * jj + 1], ph, vh[2], vh[3]);
            MMAH16816(oacc[2 * jj + 1], ph, vl[2], vl[3]);
        }
    }

    // epilogue: normalize, pack fp16
    const int grow = l >> 2;
    const int row0 = n0 + wm + grow, row1 = row0 + 8;
    __half* ob = outh + ((size_t)b * N_) * C_ + h * DH_;
#pragma unroll
    for (int nt = 0; nt < 8; nt++) {
        int col = nt * 8 + c0;
        *(uint32_t*)(ob + (size_t)row0 * C_ + col) =
            pack_h2(oacc[nt][0] * inv0, oacc[nt][1] * inv0);
        *(uint32_t*)(ob + (size_t)row1 * C_ + col) =
            pack_h2(oacc[nt][2] * inv1, oacc[nt][3] * inv1);
    }
}

// ---------------------------------------------------------------------------
// Launcher
// ---------------------------------------------------------------------------
extern "C" void kernel_launch(void* const* d_in, const int* in_sizes, int n_in,
                              void* d_out, int out_size)
{
    const float* x    = (const float*)d_in[0];
    const float* cond = (const float*)d_in[1];
    const int*   mask = (const int*)  d_in[2];
    const float* Wq   = (const float*)d_in[3];
    const float* bq   = (const float*)d_in[4];
    const float* Wkv  = (const float*)d_in[5];
    const float* bkv  = (const float*)d_in[6];
    const float* Wp   = (const float*)d_in[7];
    const float* bp   = (const float*)d_in[8];
    float* out = (float*)d_out;

    __half *qh_ptr, *attnh_ptr;
    float *kv_ptr;
    cudaGetSymbolAddress((void**)&qh_ptr,    g_qh);
    cudaGetSymbolAddress((void**)&kv_ptr,    g_kv);
    cudaGetSymbolAddress((void**)&attnh_ptr, g_attnh);

    cudaFuncSetAttribute(tc_gemm_f32a_f32c,
                         cudaFuncAttributeMaxDynamicSharedMemorySize, GEMM_SMEM);
    cudaFuncSetAttribute(tc_gemm_f32a_f16c,
                         cudaFuncAttributeMaxDynamicSharedMemorySize, GEMM_SMEM);
    cudaFuncSetAttribute(tc_gemm_f16a_f32c,
                         cudaFuncAttributeMaxDynamicSharedMemorySize, GEMM_SMEM);
    cudaFuncSetAttribute(attn_tc_kernel,
                         cudaFuncAttributeMaxDynamicSharedMemorySize, ATTN_SMEM);

    // KV projection: (1920, 2048) = cond @ Wkv^T + bkv  (fp32 out)
    {
        dim3 grid(2048 / BN, 1920 / BM);
        tc_gemm_f32a_f32c<<<grid, TPB, GEMM_SMEM>>>(cond, Wkv, bkv, kv_ptr,
                                                    1920, 2048, 1024);
    }
    // Q projection: (16384, 1024) = x @ Wq^T + bq  (fp16 out)
    {
        dim3 grid(1024 / BN, 16384 / BM);
        tc_gemm_f32a_f16c<<<grid, TPB, GEMM_SMEM>>>(x, Wq, bq, qh_ptr,
                                                    16384, 1024, 1024);
    }
    // Fused tensor-core attention (fp16 Q in, fp16 out)
    {
        dim3 grid(N_ / 128, H_, B_);
        attn_tc_kernel<<<grid, 256, ATTN_SMEM>>>(qh_ptr, kv_ptr, mask, attnh_ptr);
    }
    // Output projection: out = attn @ Wp^T + bp  (fp16 A in, fp32 out)
    {
        dim3 grid(1024 / BN, 16384 / BM);
        tc_gemm_f16a_f32c<<<grid, TPB, GEMM_SMEM>>>(attnh_ptr, Wp, bp, out,
                                                    16384, 1024, 1024);
    }
}